// round 7
// baseline (speedup 1.0000x reference)
#include <cuda_runtime.h>

#define T_LEN 2048
#define BATCH 64
#define XDIM  64
#define HID   256
#define KH    256            // recurrent K (x part precomputed)
#define KS    16             // K per warp slice

#define NCTA  128            // 2 batch-halves x 64 column-slices
#define NTHR  512            // 16 warps, warp w = k-slice [16w,16w+16)

// Static device scratch (no cudaMalloc anywhere)
__device__ float4 g_xz[(size_t)T_LEN * HID * BATCH];   // [t][col][b] pre-activations
__device__ __align__(16) float2 g_h2[2][KH][BATCH];    // tagged h: {h, tag}
__device__ unsigned g_epoch;                           // replay epoch counter

// ---------------- packed f32x2 helpers ----------------
__device__ __forceinline__ unsigned long long fma2_(unsigned long long a,
                                                    unsigned long long b,
                                                    unsigned long long c) {
    unsigned long long d;
    asm("fma.rn.f32x2 %0, %1, %2, %3;" : "=l"(d) : "l"(a), "l"(b), "l"(c));
    return d;
}
__device__ __forceinline__ unsigned long long add2_(unsigned long long a,
                                                    unsigned long long b) {
    unsigned long long d;
    asm("add.rn.f32x2 %0, %1, %2;" : "=l"(d) : "l"(a), "l"(b));
    return d;
}
__device__ __forceinline__ unsigned long long dup2_(float x) {
    unsigned long long d;
    asm("mov.b64 %0, {%1, %1};" : "=l"(d) : "r"(__float_as_uint(x)));
    return d;
}
__device__ __forceinline__ unsigned long long pack2_(float lo, float hi) {
    unsigned long long d;
    asm("mov.b64 %0, {%1, %2};" : "=l"(d) : "r"(__float_as_uint(lo)), "r"(__float_as_uint(hi)));
    return d;
}
__device__ __forceinline__ void unpack2_(unsigned long long v, float& lo, float& hi) {
    unsigned a, b;
    asm("mov.b64 {%0, %1}, %2;" : "=r"(a), "=r"(b) : "l"(v));
    lo = __uint_as_float(a); hi = __uint_as_float(b);
}
__device__ __forceinline__ float sigmoidf_(float x) {
    return 1.0f / (1.0f + __expf(-x));
}
__device__ __forceinline__ float tanh_fast_(float x) {   // 2*sigmoid(2x)-1
    return __fmaf_rn(2.0f, 1.0f / (1.0f + __expf(-2.0f * x)), -1.0f);
}

// Volatile tagged 8B load/store (single transaction -> no tearing)
__device__ __forceinline__ float2 vld2_(const float2* p) {
    float2 v;
    asm volatile("ld.volatile.global.v2.f32 {%0,%1}, [%2];"
                 : "=f"(v.x), "=f"(v.y) : "l"(p));
    return v;
}
__device__ __forceinline__ void vst2_(float2* p, float h, unsigned tag) {
    asm volatile("st.volatile.global.v2.f32 [%0], {%1,%2};"
                 :: "l"(p), "f"(h), "f"(__uint_as_float(tag)) : "memory");
}

// ---------------------------------------------------------------------------
// Pre-kernel: g_xz[t][col][b] = bias + x[b,t,:] . w_ih[4 gate rows of col, :]
// ---------------------------------------------------------------------------
#define PG_COLS 32
__global__ void __launch_bounds__(256) xz_gemm_kernel(
    const float* __restrict__ x, const float* __restrict__ w_ih,
    const float* __restrict__ bias)
{
    extern __shared__ float ps[];
    float (*xs)[65] = (float(*)[65])ps;          // [b][k], padded
    float* ws = ps + 64 * 65;                    // [c][k][q]

    const int t       = blockIdx.y;
    const int colbase = blockIdx.x * PG_COLS;
    const int tid     = threadIdx.x;

    for (int i = tid; i < 64 * 16; i += 256) {
        int b = i >> 4, k4 = i & 15;
        float4 v = *(const float4*)(x + (size_t)b * (T_LEN * XDIM) + (size_t)t * XDIM + 4 * k4);
        xs[b][4 * k4 + 0] = v.x; xs[b][4 * k4 + 1] = v.y;
        xs[b][4 * k4 + 2] = v.z; xs[b][4 * k4 + 3] = v.w;
    }
    for (int i = tid; i < PG_COLS * 64 * 4; i += 256) {
        int q = i & 3, k = (i >> 2) & 63, c = i >> 8;
        ws[i] = w_ih[(q * HID + colbase + c) * XDIM + k];
    }
    __syncthreads();

    const int b  = tid & 63;
    const int cg = tid >> 6;
    unsigned long long acc01[8], acc23[8];
    #pragma unroll
    for (int c8 = 0; c8 < 8; ++c8) {
        int col = colbase + cg * 8 + c8;
        acc01[c8] = pack2_(bias[0 * HID + col], bias[1 * HID + col]);
        acc23[c8] = pack2_(bias[2 * HID + col], bias[3 * HID + col]);
    }
    #pragma unroll 4
    for (int k = 0; k < 64; ++k) {
        unsigned long long xv = dup2_(xs[b][k]);
        #pragma unroll
        for (int c8 = 0; c8 < 8; ++c8) {
            ulonglong2 w = *(ulonglong2*)&ws[((cg * 8 + c8) * 64 + k) * 4];
            acc01[c8] = fma2_(w.x, xv, acc01[c8]);
            acc23[c8] = fma2_(w.y, xv, acc23[c8]);
        }
    }
    #pragma unroll
    for (int c8 = 0; c8 < 8; ++c8) {
        int col = colbase + cg * 8 + c8;
        float4 o;
        unpack2_(acc01[c8], o.x, o.y);
        unpack2_(acc23[c8], o.z, o.w);
        g_xz[((size_t)t * HID + col) * BATCH + b] = o;
    }
}

// ---------------------------------------------------------------------------
// Persistent LSTM, barrier-free tagged dataflow, k-sliced warps.
//   CTA (s,beta): cols [4s,4s+4), batches [32beta,32beta+32).
//   Warp w = k-slice [16w, 16w+16); lane = batch. Each thread accumulates
//   4 cols x 4 gates over its slice; tagged h consumed directly from L2
//   (loads fired with MLP=16, spin only on stale). One __syncthreads/step.
//   Warps 0-3 (one per SMSP) additionally combine/pointwise/publish col 4s+w.
// ---------------------------------------------------------------------------
__global__ void __launch_bounds__(NTHR, 1) lstm_kernel(
    const float* __restrict__ w_hh, float* __restrict__ out)
{
    extern __shared__ __align__(16) float smem[];
    float* wsm = smem;                                     // [256k][4c][4g] 16KB
    ulonglong2* part = (ulonglong2*)(smem + 4 * KH * 4);   // [2][4c][16w][32l] 64KB
    __shared__ unsigned sh_epoch;

    const int tid   = threadIdx.x;
    const int warp  = tid >> 5;
    const int lane  = tid & 31;
    const int s     = blockIdx.x & 63;
    const int beta  = blockIdx.x >> 6;
    const int b     = 32 * beta + lane;
    const bool owner = (warp < 4);
    const int col   = 4 * s + warp;                        // owners only

    if (tid == 0) sh_epoch = atomicAdd(&g_epoch, 1u) >> 7;

    // Weights: wsm[(k*4 + c)*4 + q] = w_hh[q*HID + 4s+c][k], gates i,f,g,o
    for (int idx = tid; idx < 4 * KH * 4; idx += NTHR) {
        int q = idx & 3, c = (idx >> 2) & 3, k = idx >> 4;
        wsm[idx] = w_hh[(q * HID + 4 * s + c) * HID + k];
    }
    __syncthreads();
    const unsigned epoch = sh_epoch;
    const unsigned tag0  = epoch * (unsigned)(T_LEN + 1) + 1u;  // tag(h_t) = tag0+t

    float c_reg = 0.0f;
    float4 xz = make_float4(0.f, 0.f, 0.f, 0.f);
    float2* gh2 = &g_h2[0][0][0];
    if (owner) {
        vst2_(gh2 + (size_t)col * BATCH + b, 0.0f, tag0);       // h(0)=0, slot 0
        xz = __ldcg(&g_xz[(size_t)col * BATCH + b]);            // xz(t=0)
    }

    const int k0 = warp * KS;
    const ulonglong2* wv = (const ulonglong2*)wsm + k0 * 4;     // [i*4 + c]
    const size_t out_base = (size_t)b * (T_LEN * HID) + col;

    for (int t = 0; t < T_LEN; ++t) {
        const unsigned exp = tag0 + (unsigned)t;
        const float2* src = gh2 + (size_t)(t & 1) * (KH * BATCH) + k0 * BATCH + b;
        ulonglong2* pslot = part + (size_t)(t & 1) * (4 * 16 * 32);

        // Fire all 16 tagged loads (256B/warp each, coalesced), then consume;
        // re-spin only stale values (producer publish overlaps our FMA work).
        float2 hv[KS];
        #pragma unroll
        for (int i = 0; i < KS; ++i) hv[i] = vld2_(src + i * BATCH);

        unsigned long long a01[4] = {0ull, 0ull, 0ull, 0ull};
        unsigned long long a23[4] = {0ull, 0ull, 0ull, 0ull};
        #pragma unroll
        for (int i = 0; i < KS; ++i) {
            while (__float_as_uint(hv[i].y) != exp)
                hv[i] = vld2_(src + i * BATCH);
            unsigned long long h2 = dup2_(hv[i].x);
            #pragma unroll
            for (int c = 0; c < 4; ++c) {
                ulonglong2 w = wv[i * 4 + c];
                a01[c] = fma2_(w.x, h2, a01[c]);
                a23[c] = fma2_(w.y, h2, a23[c]);
            }
        }
        #pragma unroll
        for (int c = 0; c < 4; ++c) {
            ulonglong2 v; v.x = a01[c]; v.y = a23[c];
            pslot[(c * 16 + warp) * 32 + lane] = v;             // 512B coalesced
        }
        __syncthreads();                                        // partials ready

        if (owner) {
            unsigned long long acc01 = pack2_(xz.x, xz.y);      // x-part + bias
            unsigned long long acc23 = pack2_(xz.z, xz.w);
            #pragma unroll
            for (int w = 0; w < 16; ++w) {
                ulonglong2 p = pslot[(warp * 16 + w) * 32 + lane];
                acc01 = add2_(acc01, p.x);
                acc23 = add2_(acc23, p.y);
            }
            float a0, a1, a2, a3;
            unpack2_(acc01, a0, a1);
            unpack2_(acc23, a2, a3);

            const float ig = sigmoidf_(a0);
            const float fg = sigmoidf_(a1);
            const float gg = tanh_fast_(a2);
            const float og = sigmoidf_(a3);
            c_reg = fmaf(fg, c_reg, ig * gg);
            const float h = og * tanh_fast_(c_reg);

            // Publish FIRST (consumers are spinning on this), then sidebands.
            vst2_(gh2 + (size_t)((t + 1) & 1) * (KH * BATCH) + (size_t)col * BATCH + b,
                  h, exp + 1u);
            out[out_base + (size_t)t * HID] = h;
            if (t + 1 < T_LEN)
                xz = __ldcg(&g_xz[((size_t)(t + 1) * HID + col) * BATCH + b]);
        }
        // No trailing barrier: part is double-buffered (t&1); h-tag spins of
        // step t+1 cannot pass until owners publish, which follows their
        // combine reads of pslot(t) -> WAR-safe at depth 2.
    }
}

// ---------------------------------------------------------------------------
extern "C" void kernel_launch(void* const* d_in, const int* in_sizes, int n_in,
                              void* d_out, int out_size) {
    (void)in_sizes; (void)n_in; (void)out_size;
    const float* x    = (const float*)d_in[0];
    const float* w_ih = (const float*)d_in[1];
    const float* w_hh = (const float*)d_in[2];
    const float* bias = (const float*)d_in[3];
    float* out = (float*)d_out;

    const int pg_smem = (64 * 65 + PG_COLS * 64 * 4) * (int)sizeof(float);
    cudaFuncSetAttribute(xz_gemm_kernel,
                         cudaFuncAttributeMaxDynamicSharedMemorySize, pg_smem);
    const int ls_smem = 4 * KH * 4 * (int)sizeof(float)
                        + 2 * 4 * 16 * 32 * (int)sizeof(ulonglong2);  // 16KB+64KB
    cudaFuncSetAttribute(lstm_kernel,
                         cudaFuncAttributeMaxDynamicSharedMemorySize, ls_smem);

    dim3 pg_grid(HID / PG_COLS, T_LEN);
    xz_gemm_kernel<<<pg_grid, 256, pg_smem>>>(x, w_ih, bias);
    lstm_kernel<<<NCTA, NTHR, ls_smem>>>(w_hh, out);
}

// round 8
// speedup vs baseline: 1.2144x; 1.2144x over previous
#include <cuda_runtime.h>

#define T_LEN 2048
#define BATCH 64
#define XDIM  64
#define HID   256
#define KH    256            // recurrent K (x part precomputed)
#define KQ    64             // K per quarter-warp

#define NCTA  128            // 2 batch-halves x 64 column-slices
#define NTHR  512            // 16 warps: (warp&3)=column, (warp>>2)=K-quarter

// Static device scratch (no cudaMalloc anywhere)
__device__ float4 g_xz[(size_t)T_LEN * HID * BATCH];   // [t][col][b] pre-activations
// Tagged h exchange: float2 {h, tag} per value, viewed as float4 (2 batches)
__device__ __align__(16) float4 g_h2[2][KH][BATCH / 2];
__device__ unsigned g_epoch;                           // replay epoch counter

// ---------------- packed f32x2 helpers ----------------
__device__ __forceinline__ unsigned long long fma2_(unsigned long long a,
                                                    unsigned long long b,
                                                    unsigned long long c) {
    unsigned long long d;
    asm("fma.rn.f32x2 %0, %1, %2, %3;" : "=l"(d) : "l"(a), "l"(b), "l"(c));
    return d;
}
__device__ __forceinline__ unsigned long long add2_(unsigned long long a,
                                                    unsigned long long b) {
    unsigned long long d;
    asm("add.rn.f32x2 %0, %1, %2;" : "=l"(d) : "l"(a), "l"(b));
    return d;
}
__device__ __forceinline__ unsigned long long dup2_(float x) {
    unsigned long long d;
    asm("mov.b64 %0, {%1, %1};" : "=l"(d) : "r"(__float_as_uint(x)));
    return d;
}
__device__ __forceinline__ unsigned long long pack2_(float lo, float hi) {
    unsigned long long d;
    asm("mov.b64 %0, {%1, %2};" : "=l"(d) : "r"(__float_as_uint(lo)), "r"(__float_as_uint(hi)));
    return d;
}
__device__ __forceinline__ void unpack2_(unsigned long long v, float& lo, float& hi) {
    unsigned a, b;
    asm("mov.b64 {%0, %1}, %2;" : "=r"(a), "=r"(b) : "l"(v));
    lo = __uint_as_float(a); hi = __uint_as_float(b);
}
__device__ __forceinline__ float sigmoidf_(float x) {
    return 1.0f / (1.0f + __expf(-x));
}
__device__ __forceinline__ float tanh_fast_(float x) {   // 2*sigmoid(2x)-1
    return __fmaf_rn(2.0f, 1.0f / (1.0f + __expf(-2.0f * x)), -1.0f);
}

// Volatile 16B load (2 tagged h values); never hoisted/cached
__device__ __forceinline__ float4 vld4_(const float4* p) {
    float4 v;
    asm volatile("ld.volatile.global.v4.f32 {%0,%1,%2,%3}, [%4];"
                 : "=f"(v.x), "=f"(v.y), "=f"(v.z), "=f"(v.w) : "l"(p));
    return v;
}
// Publish one tagged h value (8B single transaction -> no tearing)
__device__ __forceinline__ void vst2_(float2* p, float h, unsigned tag) {
    asm volatile("st.volatile.global.v2.f32 [%0], {%1,%2};"
                 :: "l"(p), "f"(h), "f"(__uint_as_float(tag)) : "memory");
}

// ---------------------------------------------------------------------------
// Pre-kernel: g_xz[t][col][b] = bias + x[b,t,:] . w_ih[4 gate rows of col, :]
// ---------------------------------------------------------------------------
#define PG_COLS 32
__global__ void __launch_bounds__(256) xz_gemm_kernel(
    const float* __restrict__ x, const float* __restrict__ w_ih,
    const float* __restrict__ bias)
{
    extern __shared__ float ps[];
    float (*xs)[65] = (float(*)[65])ps;          // [b][k], padded
    float* ws = ps + 64 * 65;                    // [c][k][q]

    const int t       = blockIdx.y;
    const int colbase = blockIdx.x * PG_COLS;
    const int tid     = threadIdx.x;

    for (int i = tid; i < 64 * 16; i += 256) {
        int b = i >> 4, k4 = i & 15;
        float4 v = *(const float4*)(x + (size_t)b * (T_LEN * XDIM) + (size_t)t * XDIM + 4 * k4);
        xs[b][4 * k4 + 0] = v.x; xs[b][4 * k4 + 1] = v.y;
        xs[b][4 * k4 + 2] = v.z; xs[b][4 * k4 + 3] = v.w;
    }
    for (int i = tid; i < PG_COLS * 64 * 4; i += 256) {
        int q = i & 3, k = (i >> 2) & 63, c = i >> 8;
        ws[i] = w_ih[(q * HID + colbase + c) * XDIM + k];
    }
    __syncthreads();

    const int b  = tid & 63;
    const int cg = tid >> 6;
    unsigned long long acc01[8], acc23[8];
    #pragma unroll
    for (int c8 = 0; c8 < 8; ++c8) {
        int col = colbase + cg * 8 + c8;
        acc01[c8] = pack2_(bias[0 * HID + col], bias[1 * HID + col]);
        acc23[c8] = pack2_(bias[2 * HID + col], bias[3 * HID + col]);
    }
    #pragma unroll 4
    for (int k = 0; k < 64; ++k) {
        unsigned long long xv = dup2_(xs[b][k]);
        #pragma unroll
        for (int c8 = 0; c8 < 8; ++c8) {
            ulonglong2 w = *(ulonglong2*)&ws[((cg * 8 + c8) * 64 + k) * 4];
            acc01[c8] = fma2_(w.x, xv, acc01[c8]);
            acc23[c8] = fma2_(w.y, xv, acc23[c8]);
        }
    }
    #pragma unroll
    for (int c8 = 0; c8 < 8; ++c8) {
        int col = colbase + cg * 8 + c8;
        float4 o;
        unpack2_(acc01[c8], o.x, o.y);
        unpack2_(acc23[c8], o.z, o.w);
        g_xz[((size_t)t * HID + col) * BATCH + b] = o;
    }
}

// ---------------------------------------------------------------------------
// Persistent LSTM, barrier-free tagged dataflow (R6 layout).
//   CTA (s,beta): cols [4s,4s+4), batches [32beta,32beta+32).
//   warp w: col 4s+(w&3), K-quarter (w>>2). h values tagged with step number;
//   staging uses ROUND-BASED polling (all pending loads re-fired together,
//   MLP=8/round). hs double-buffered by t&1 -> single __syncthreads per step.
// ---------------------------------------------------------------------------
__global__ void __launch_bounds__(NTHR, 1) lstm_kernel(
    const float* __restrict__ w_hh, float* __restrict__ out)
{
    extern __shared__ __align__(16) float smem[];
    float* wsm = smem;                                   // [4c][256k][4g] 16KB
    float* hs  = smem + 4 * KH * 4;                      // [2][256k][32b] 64KB
    ulonglong2* part = (ulonglong2*)(hs + 2 * KH * 32);  // [3][4c][32l]    6KB
    __shared__ unsigned sh_epoch;

    const int tid   = threadIdx.x;
    const int warp  = tid >> 5;
    const int lane  = tid & 31;
    const int colw  = warp & 3;
    const int kq    = warp >> 2;          // 0..3
    const int s     = blockIdx.x & 63;
    const int beta  = blockIdx.x >> 6;
    const int col   = 4 * s + colw;
    const int b     = 32 * beta + lane;
    const bool owner = (kq == 0);

    if (tid == 0) sh_epoch = atomicAdd(&g_epoch, 1u) >> 7;   // /NCTA -> replay id

    // Recurrent weights: wsm[((colw*256 + k)*4) + q], gate order i,f,g,o
    for (int idx = tid; idx < 4 * KH * 4; idx += NTHR) {
        int q  = idx & 3;
        int kk = (idx >> 2) & 255;
        int cw = idx >> 10;
        wsm[idx] = w_hh[(q * HID + 4 * s + cw) * HID + kk];
    }
    __syncthreads();
    const unsigned epoch = sh_epoch;
    const unsigned tag0  = epoch * (unsigned)(T_LEN + 1) + 1u;  // tag(h_t)=tag0+t

    float c_reg = 0.0f;
    float4 xz = make_float4(0.f, 0.f, 0.f, 0.f);
    float2* gh2 = (float2*)g_h2;
    if (owner) {
        vst2_(gh2 + ((size_t)0 * KH + col) * BATCH + b, 0.0f, tag0);  // h(0)=0
        xz = __ldcg(&g_xz[(size_t)col * BATCH + b]);                  // xz(t=0)
    }

    const ulonglong2* wr = (const ulonglong2*)wsm + (colw * KH + kq * KQ);
    const size_t out_base = (size_t)b * (T_LEN * HID) + col;
    const float4* ghv_base = &g_h2[0][0][0];

    // Per-thread staging coordinates (fixed): 4096 float4 / 512 thr = 8 each
    int kk_[8], bp_[8];
    #pragma unroll
    for (int i = 0; i < 8; ++i) {
        int idx = tid + i * NTHR;              // 0..4095
        kk_[i] = idx >> 4;                     // k
        bp_[i] = idx & 15;                     // batch-pair within half
    }

    for (int t = 0; t < T_LEN; ++t) {
        const unsigned exp = tag0 + (unsigned)t;
        const float4* src = ghv_base + (size_t)(t & 1) * KH * (BATCH / 2)
                          + 16 * beta;
        float* hbuf = hs + (size_t)(t & 1) * (KH * 32);

        // Round-based tagged staging: fire all 8, then re-fire pending sets
        // together (MLP=8 per round) until every tag matches.
        float4 v[8];
        #pragma unroll
        for (int i = 0; i < 8; ++i) v[i] = vld4_(src + kk_[i] * (BATCH / 2) + bp_[i]);
        unsigned pend = 0xffu;
        while (true) {
            #pragma unroll
            for (int i = 0; i < 8; ++i) {
                if (pend & (1u << i)) {
                    if (__float_as_uint(v[i].y) == exp &&
                        __float_as_uint(v[i].w) == exp) {
                        *(float2*)&hbuf[kk_[i] * 32 + 2 * bp_[i]] =
                            make_float2(v[i].x, v[i].z);
                        pend &= ~(1u << i);
                    }
                }
            }
            if (!pend) break;
            #pragma unroll
            for (int i = 0; i < 8; ++i)
                if (pend & (1u << i))
                    v[i] = vld4_(src + kk_[i] * (BATCH / 2) + bp_[i]);
        }
        __syncthreads();   // hs(t) fully staged (also orders part/hs reuse)

        // K-quarter GEMV: per k = LDS.32 + LDS.128 + dup + 2 FFMA2
        const float* xb = hbuf + kq * KQ * 32 + lane;
        unsigned long long acc01 = 0ull, acc23 = 0ull;
        #pragma unroll 8
        for (int k = 0; k < KQ; ++k) {
            unsigned long long hv2 = dup2_(xb[k * 32]);
            ulonglong2 w = wr[k];
            acc01 = fma2_(w.x, hv2, acc01);
            acc23 = fma2_(w.y, hv2, acc23);
        }

        if (!owner) {
            ulonglong2 pv; pv.x = acc01; pv.y = acc23;
            part[((kq - 1) * 4 + colw) * 32 + lane] = pv;
        }
        asm volatile("bar.sync %0, 128;" :: "r"(1 + colw) : "memory");

        if (owner) {
            #pragma unroll
            for (int q = 0; q < 3; ++q) {
                ulonglong2 p = part[(q * 4 + colw) * 32 + lane];
                acc01 = add2_(acc01, p.x);
                acc23 = add2_(acc23, p.y);
            }
            acc01 = add2_(acc01, pack2_(xz.x, xz.y));     // + x-part + bias
            acc23 = add2_(acc23, pack2_(xz.z, xz.w));
            float a0, a1, a2, a3;
            unpack2_(acc01, a0, a1);
            unpack2_(acc23, a2, a3);

            const float ig = sigmoidf_(a0);
            const float fg = sigmoidf_(a1);
            const float gg = tanh_fast_(a2);
            const float og = sigmoidf_(a3);
            c_reg = fmaf(fg, c_reg, ig * gg);
            const float h = og * tanh_fast_(c_reg);

            // Publish FIRST (consumers spin on this), then sideband stores.
            vst2_(gh2 + ((size_t)((t + 1) & 1) * KH + col) * BATCH + b,
                  h, exp + 1u);
            out[out_base + (size_t)t * HID] = h;
            if (t + 1 < T_LEN)
                xz = __ldcg(&g_xz[((size_t)(t + 1) * HID + col) * BATCH + b]);
        }
        // No trailing barrier: hs and the h exchange are both depth-2
        // buffered; next step's tag spins + the staging __syncthreads give
        // all required ordering (see R6/R8 WAR proofs).
    }
}

// ---------------------------------------------------------------------------
extern "C" void kernel_launch(void* const* d_in, const int* in_sizes, int n_in,
                              void* d_out, int out_size) {
    (void)in_sizes; (void)n_in; (void)out_size;
    const float* x    = (const float*)d_in[0];
    const float* w_ih = (const float*)d_in[1];
    const float* w_hh = (const float*)d_in[2];
    const float* bias = (const float*)d_in[3];
    float* out = (float*)d_out;

    const int pg_smem = (64 * 65 + PG_COLS * 64 * 4) * (int)sizeof(float);
    cudaFuncSetAttribute(xz_gemm_kernel,
                         cudaFuncAttributeMaxDynamicSharedMemorySize, pg_smem);
    const int ls_smem = (4 * KH * 4 + 2 * KH * 32) * (int)sizeof(float)
                        + 3 * 4 * 32 * (int)sizeof(ulonglong2);   // 16+64+6 KB
    cudaFuncSetAttribute(lstm_kernel,
                         cudaFuncAttributeMaxDynamicSharedMemorySize, ls_smem);

    dim3 pg_grid(HID / PG_COLS, T_LEN);
    xz_gemm_kernel<<<pg_grid, 256, pg_smem>>>(x, w_ih, bias);
    lstm_kernel<<<NCTA, NTHR, ls_smem>>>(w_hh, out);
}